// round 10
// baseline (speedup 1.0000x reference)
#include <cuda_runtime.h>

#define NB 4
#define NC 64
#define HW 40
#define KS 11
#define HP 30
#define PIX 1600          // 40*40
#define NDX 15            // dx shifts per block (4 groups; last has 14 live)
#define NG 8
#define GUARD 64
#define OUTN (NB*HP*HP)
#define SQSTRIDE 2000     // 50 rows * 40 cols per d
#define TOTBLK (4*30*NB)  // 480 corr blocks

__device__ unsigned g_enc[OUTN];
__device__ float    g_inv[OUTN];
__device__ float    g_part[NB*NG*PIX];
__device__ unsigned g_done;
__device__ __align__(16) float g_im2g[GUARD + NB*NC*PIX + GUARD];

__device__ __forceinline__ unsigned encf(float f){
    int b = __float_as_int(f);
    return (unsigned)(b ^ ((b >> 31) | 0x80000000));
}

// ---------------- K0a: partial sum-of-squares + guarded im2 copy + counter reset ----
__global__ void __launch_bounds__(256) prep_kernel(const float* __restrict__ im1,
                                                   const float* __restrict__ im2){
    int blk = blockIdx.x;
    if (blk < NB*NG){
        int b = blk >> 3, g = blk & 7;
        const float* base = im1 + ((size_t)b*NC + g*(NC/NG))*PIX;
        for (int p = threadIdx.x; p < PIX; p += 256){
            float acc = 0.f;
            #pragma unroll
            for (int c = 0; c < NC/NG; ++c){ float v = base[c*PIX + p]; acc += v*v; }
            g_part[(b*NG + g)*PIX + p] = acc;
        }
    } else {
        int cb = blk - NB*NG;                  // 0..31
        const int total4 = (NB*NC*PIX)/4;
        const float4* src = (const float4*)im2;
        float4* dst = (float4*)(g_im2g + GUARD);
        for (int i = cb*256 + threadIdx.x; i < total4; i += 32*256)
            dst[i] = src[i];
        if (cb == 0){
            for (int i = threadIdx.x; i < GUARD; i += 256){
                g_im2g[i] = 0.f;
                g_im2g[GUARD + NB*NC*PIX + i] = 0.f;
            }
            if (threadIdx.x == 0) g_done = 0u;
        }
    }
}

// ---------------- K0b: reduce partials + 11x11 box sum -> inv norm ----------------
__global__ void __launch_bounds__(1024) norm_reduce(){
    __shared__ float sA[PIX];
    __shared__ float sH[HW*HP];
    int b = blockIdx.x;
    int tid = threadIdx.x;
    for (int p = tid; p < PIX; p += 1024){
        float acc = 0.f;
        #pragma unroll
        for (int g = 0; g < NG; ++g) acc += g_part[(b*NG + g)*PIX + p];
        sA[p] = acc;
    }
    __syncthreads();
    for (int t = tid; t < HW*HP; t += 1024){
        int y = t / HP, lx = t - y*HP;
        const float* row = &sA[y*HW];
        float s = 0.f;
        #pragma unroll
        for (int j = 0; j < KS; ++j) s += row[lx + j];
        sH[y*HP + lx] = s;
    }
    __syncthreads();
    for (int t = tid; t < HP*HP; t += 1024){
        int ly = t / HP, lx = t - ly*HP;
        float s = 0.f;
        #pragma unroll
        for (int i = 0; i < KS; ++i) s += sH[(ly+i)*HP + lx];
        float nrm = sqrtf(s);
        g_inv[b*HP*HP + t] = 1.0f / fmaxf(nrm, 1e-4f);
        g_enc[b*HP*HP + t] = 0u;
    }
}

// ---------------- mainloop: direct-LDG, zero barriers, L1 prefetch ----------------
template<int SH>
__device__ __forceinline__ void run_channels(
    const float* __restrict__ g1c,    // &im1[b][0][i1]
    const float* __restrict__ wpc,    // guarded im2 ptr at window start (16B aligned)
    float* __restrict__ q)
{
    #pragma unroll 1
    for (int c = 0; c < NC; ++c){
        float4 A = __ldg((const float4*)(g1c + (size_t)c*PIX));
        float w[24];
        #pragma unroll
        for (int k = 0; k < 6; ++k){
            float4 tv = __ldg((const float4*)(wpc + (size_t)c*PIX + 4*k));
            w[4*k+0]=tv.x; w[4*k+1]=tv.y; w[4*k+2]=tv.z; w[4*k+3]=tv.w;
        }
        if (c + 1 < NC){   // pull next channel's lines into L1 before the FMA burst
            asm volatile("prefetch.global.L1 [%0];" :: "l"(g1c + (size_t)(c+1)*PIX));
            asm volatile("prefetch.global.L1 [%0];" :: "l"(wpc + (size_t)(c+1)*PIX));
            asm volatile("prefetch.global.L1 [%0];" :: "l"(wpc + (size_t)(c+1)*PIX + 16));
        }
        #pragma unroll
        for (int d = 0; d < NDX; ++d){
            q[d*4+0] += A.x * w[SH+d+0];
            q[d*4+1] += A.y * w[SH+d+1];
            q[d*4+2] += A.z * w[SH+d+2];
            q[d*4+3] += A.w * w[SH+d+3];
        }
    }
}

// ---------------- K1: paired-dy correlation, single merged epilogue ----------------
// grid: (4 dx-groups, 30 dy-pairs, 4 batch), 512 threads
__global__ void __launch_bounds__(512, 1) corr_kernel(const float* __restrict__ im1,
                                                      float* __restrict__ out){
    extern __shared__ float smem[];
    float* sq   = smem;                  // [NDX][50][40]
    float* sinv = sq + NDX*SQSTRIDE;     // [900]

    int tid = threadIdx.x;
    int gx  = blockIdx.x;
    int p   = blockIdx.y;
    int b   = blockIdx.z;
    int dxlo = -29 + NDX*gx;

    // dyA = p-29 (<=0), dyB = p+1 (>0); p==29 -> single region dy=0
    int dyA, dyB, cntA, cntB, nrowsA, nrowsB;
    if (p < 29){ dyA = p - 29; dyB = p + 1; nrowsA = 11+p; nrowsB = 39-p; }
    else       { dyA = 0;      dyB = 0;     nrowsA = 40;   nrowsB = 0;   }
    cntA = nrowsA*10; cntB = nrowsB*10;
    int nrTot = nrowsA + nrowsB;

    for (int i = tid; i < HP*HP; i += 512) sinv[i] = g_inv[b*HP*HP + i];

    bool act = tid < cntA + cntB;
    int myDy, s, rBase;
    if (tid < cntA){ myDy = dyA; s = tid; rBase = 0; }
    else           { myDy = dyB; s = tid - cntA; rBase = nrowsA; }
    int y0t = (myDy < 0) ? -myDy : 0;
    int rr = s/10;
    int sy = y0t + rr;
    int sx = (s - rr*10)*4;
    int rD = rBase + rr;                 // row slot in merged sq

    const float* g1c = im1 + (size_t)b*NC*PIX + sy*HW + sx;
    const float* wbase = g_im2g + GUARD + (size_t)b*NC*PIX + (sy + myDy)*HW + sx + dxlo;

    float q[NDX*4];
    #pragma unroll
    for (int i = 0; i < NDX*4; ++i) q[i] = 0.f;

    if (act){
        switch (gx){
            case 0: run_channels<3>(g1c, wbase-3, q); break;
            case 1: run_channels<6>(g1c, wbase-6, q); break;
            case 2: run_channels<5>(g1c, wbase-5, q); break;
            default: run_channels<4>(g1c, wbase-4, q); break;
        }
    }

    // ---- dump both regions into merged sq ----
    if (act){
        #pragma unroll
        for (int d = 0; d < NDX; ++d)
            *(float4*)&sq[d*SQSTRIDE + rD*HW + sx] = make_float4(q[d*4+0],q[d*4+1],q[d*4+2],q[d*4+3]);
    }
    __syncthreads();

    // ---- horizontal 11-sum over all 50 rows, in place (cols 0..29) ----
    for (int t = tid; t < NDX*nrTot; t += 512){
        int d = t / nrTot, r = t - (t/nrTot)*nrTot;
        float* row = &sq[d*SQSTRIDE + r*HW];
        float v[HW];
        #pragma unroll
        for (int k = 0; k < HW/4; ++k){
            float4 tv = *(const float4*)&row[4*k];
            v[4*k+0]=tv.x; v[4*k+1]=tv.y; v[4*k+2]=tv.z; v[4*k+3]=tv.w;
        }
        float su = 0.f;
        #pragma unroll
        for (int j = 0; j < KS; ++j) su += v[j];
        row[0] = su;
        #pragma unroll
        for (int lx = 1; lx < HP; ++lx){
            su += v[lx+KS-1] - v[lx-1];
            row[lx] = su;
        }
    }
    __syncthreads();

    // ---- vertical 11-sum per (region, d, lx), in place ----
    for (int t = tid; t < 2*NDX*HP; t += 512){
        int rg  = t / (NDX*HP);
        int rem = t - rg*NDX*HP;
        int d = rem / HP, lx = rem - (rem/HP)*HP;
        int nrows = rg ? nrowsB : nrowsA;
        if (nrows == 0) continue;
        int rb = rg ? nrowsA : 0;
        int nly = nrows - (KS-1);
        float* colp = &sq[d*SQSTRIDE + lx];
        float v[HW];
        #pragma unroll
        for (int i = 0; i < HW; ++i) v[i] = (i < nrows) ? colp[(rb+i)*HW] : 0.f;
        float su = 0.f;
        #pragma unroll
        for (int j = 0; j < KS; ++j) su += v[j];
        #pragma unroll
        for (int o = 0; o < HP; ++o){
            if (o < nly) colp[(rb+o)*HW] = su;
            if (o+1 < HP) su += v[o+KS] - v[o];
        }
    }
    __syncthreads();

    // ---- per-output max over this block's dx set (exactly one region per py) ----
    unsigned* eout = &g_enc[b*HP*HP];
    for (int t = tid; t < HP*HP; t += 512){
        int py = t / HP, px = t - (t/HP)*HP;
        int rowSlot, ly;
        if (py <= p && p < 29){ rowSlot = py;                 ly = py - dyA; }
        else if (p >= 29)     { rowSlot = py;                 ly = py;       }
        else                  { rowSlot = nrowsA + (py-p-1);  ly = py - dyB; }
        if (ly < 0 || ly >= HP) continue;
        const float* base = &sq[rowSlot*HW];
        const float* svr  = &sinv[ly*HP];
        float m = -3.0e38f;
        bool any = false;
        #pragma unroll
        for (int d = 0; d < NDX; ++d){
            int dx = dxlo + d;
            int lx = px - dx;
            if (dx <= 29 && lx >= 0 && lx < HP){
                float v = base[d*SQSTRIDE + lx] * svr[lx];
                m = fmaxf(m, v);
                any = true;
            }
        }
        if (any) atomicMax(&eout[t], encf(m));
    }

    // ---- last block decodes ----
    __threadfence();
    __shared__ unsigned sLast;
    if (tid == 0) sLast = atomicAdd(&g_done, 1u);
    __syncthreads();
    if (sLast == TOTBLK - 1){
        for (int t = tid; t < OUTN; t += 512){
            unsigned e = g_enc[t];
            int v = (e & 0x80000000u) ? (int)(e ^ 0x80000000u) : ~(int)e;
            out[t] = __int_as_float(v);
        }
    }
}

extern "C" void kernel_launch(void* const* d_in, const int* in_sizes, int n_in,
                              void* d_out, int out_size){
    (void)in_sizes; (void)n_in; (void)out_size;
    const float* im1 = (const float*)d_in[0];
    const float* im2 = (const float*)d_in[1];

    const int smem_bytes = (NDX*SQSTRIDE + HP*HP) * (int)sizeof(float);
    cudaFuncSetAttribute(corr_kernel, cudaFuncAttributeMaxDynamicSharedMemorySize, smem_bytes);

    prep_kernel<<<64, 256>>>(im1, im2);
    norm_reduce<<<NB, 1024>>>();
    corr_kernel<<<dim3(4, 30, NB), 512, smem_bytes>>>(im1, (float*)d_out);
}

// round 11
// speedup vs baseline: 1.0204x; 1.0204x over previous
#include <cuda_runtime.h>

#define NB 4
#define NC 64
#define HW 40
#define KS 11
#define HP 30
#define PIX 1600          // 40*40
#define NDX 15            // dx shifts per block (4 groups; last has 14 live)
#define NG 8
#define GUARD 64
#define OUTN (NB*HP*HP)
#define SQSTRIDE 2000     // 50 rows * 40 cols per d
#define TOTBLK (4*30*NB)  // 480 corr blocks

__device__ unsigned g_enc[OUTN];
__device__ float    g_inv[OUTN];
__device__ float    g_part[NB*NG*PIX];
__device__ unsigned g_done;
__device__ __align__(16) float g_im2g[GUARD + NB*NC*PIX + GUARD];

__device__ __forceinline__ unsigned encf(float f){
    int b = __float_as_int(f);
    return (unsigned)(b ^ ((b >> 31) | 0x80000000));
}

// ---------------- K0a: partial sum-of-squares + guarded im2 copy + counter reset ----
__global__ void __launch_bounds__(256) prep_kernel(const float* __restrict__ im1,
                                                   const float* __restrict__ im2){
    int blk = blockIdx.x;
    if (blk < NB*NG){
        int b = blk >> 3, g = blk & 7;
        const float* base = im1 + ((size_t)b*NC + g*(NC/NG))*PIX;
        for (int p = threadIdx.x; p < PIX; p += 256){
            float acc = 0.f;
            #pragma unroll
            for (int c = 0; c < NC/NG; ++c){ float v = base[c*PIX + p]; acc += v*v; }
            g_part[(b*NG + g)*PIX + p] = acc;
        }
    } else {
        int cb = blk - NB*NG;                  // 0..31
        const int total4 = (NB*NC*PIX)/4;
        const float4* src = (const float4*)im2;
        float4* dst = (float4*)(g_im2g + GUARD);
        for (int i = cb*256 + threadIdx.x; i < total4; i += 32*256)
            dst[i] = src[i];
        if (cb == 0){
            for (int i = threadIdx.x; i < GUARD; i += 256){
                g_im2g[i] = 0.f;
                g_im2g[GUARD + NB*NC*PIX + i] = 0.f;
            }
            if (threadIdx.x == 0) g_done = 0u;
        }
    }
}

// ---------------- K0b: reduce partials + 11x11 box sum -> inv norm ----------------
__global__ void __launch_bounds__(1024) norm_reduce(){
    __shared__ float sA[PIX];
    __shared__ float sH[HW*HP];
    int b = blockIdx.x;
    int tid = threadIdx.x;
    for (int p = tid; p < PIX; p += 1024){
        float acc = 0.f;
        #pragma unroll
        for (int g = 0; g < NG; ++g) acc += g_part[(b*NG + g)*PIX + p];
        sA[p] = acc;
    }
    __syncthreads();
    for (int t = tid; t < HW*HP; t += 1024){
        int y = t / HP, lx = t - y*HP;
        const float* row = &sA[y*HW];
        float s = 0.f;
        #pragma unroll
        for (int j = 0; j < KS; ++j) s += row[lx + j];
        sH[y*HP + lx] = s;
    }
    __syncthreads();
    for (int t = tid; t < HP*HP; t += 1024){
        int ly = t / HP, lx = t - ly*HP;
        float s = 0.f;
        #pragma unroll
        for (int i = 0; i < KS; ++i) s += sH[(ly+i)*HP + lx];
        float nrm = sqrtf(s);
        g_inv[b*HP*HP + t] = 1.0f / fmaxf(nrm, 1e-4f);
        g_enc[b*HP*HP + t] = 0u;
    }
}

// ---------------- mainloop: direct-LDG, zero barriers ----------------
template<int SH>
__device__ __forceinline__ void run_channels(
    const float* __restrict__ g1c,    // &im1[b][0][i1]
    const float* __restrict__ wpc,    // guarded im2 ptr at window start (16B aligned)
    float* __restrict__ q)
{
    #pragma unroll 1
    for (int c = 0; c < NC; ++c){
        float4 A = __ldg((const float4*)(g1c + (size_t)c*PIX));
        float w[24];
        #pragma unroll
        for (int k = 0; k < 6; ++k){
            float4 tv = __ldg((const float4*)(wpc + (size_t)c*PIX + 4*k));
            w[4*k+0]=tv.x; w[4*k+1]=tv.y; w[4*k+2]=tv.z; w[4*k+3]=tv.w;
        }
        #pragma unroll
        for (int d = 0; d < NDX; ++d){
            q[d*4+0] += A.x * w[SH+d+0];
            q[d*4+1] += A.y * w[SH+d+1];
            q[d*4+2] += A.z * w[SH+d+2];
            q[d*4+3] += A.w * w[SH+d+3];
        }
    }
}

// ---------------- K1: paired-dy correlation, single merged epilogue ----------------
// grid: (4 dx-groups, 30 dy-pairs, 4 batch), 512 threads
__global__ void __launch_bounds__(512, 1) corr_kernel(const float* __restrict__ im1,
                                                      float* __restrict__ out){
    extern __shared__ float smem[];
    float* sq   = smem;                  // [NDX][50][40]
    float* sinv = sq + NDX*SQSTRIDE;     // [900]

    int tid = threadIdx.x;
    int gx  = blockIdx.x;
    int p   = blockIdx.y;
    int b   = blockIdx.z;
    int dxlo = -29 + NDX*gx;

    // dyA = p-29 (<=0), dyB = p+1 (>0); p==29 -> single region dy=0
    int dyA, dyB, cntA, cntB, nrowsA, nrowsB;
    if (p < 29){ dyA = p - 29; dyB = p + 1; nrowsA = 11+p; nrowsB = 39-p; }
    else       { dyA = 0;      dyB = 0;     nrowsA = 40;   nrowsB = 0;   }
    cntA = nrowsA*10; cntB = nrowsB*10;
    int nrTot = nrowsA + nrowsB;

    for (int i = tid; i < HP*HP; i += 512) sinv[i] = g_inv[b*HP*HP + i];

    bool act = tid < cntA + cntB;
    int myDy, s, rBase;
    if (tid < cntA){ myDy = dyA; s = tid; rBase = 0; }
    else           { myDy = dyB; s = tid - cntA; rBase = nrowsA; }
    int y0t = (myDy < 0) ? -myDy : 0;
    int rr = s/10;
    int sy = y0t + rr;
    int sx = (s - rr*10)*4;
    int rD = rBase + rr;                 // row slot in merged sq

    const float* g1c = im1 + (size_t)b*NC*PIX + sy*HW + sx;
    const float* wbase = g_im2g + GUARD + (size_t)b*NC*PIX + (sy + myDy)*HW + sx + dxlo;

    float q[NDX*4];
    #pragma unroll
    for (int i = 0; i < NDX*4; ++i) q[i] = 0.f;

    if (act){
        switch (gx){
            case 0: run_channels<3>(g1c, wbase-3, q); break;
            case 1: run_channels<6>(g1c, wbase-6, q); break;
            case 2: run_channels<5>(g1c, wbase-5, q); break;
            default: run_channels<4>(g1c, wbase-4, q); break;
        }
    }

    // ---- dump both regions into merged sq ----
    if (act){
        #pragma unroll
        for (int d = 0; d < NDX; ++d)
            *(float4*)&sq[d*SQSTRIDE + rD*HW + sx] = make_float4(q[d*4+0],q[d*4+1],q[d*4+2],q[d*4+3]);
    }
    __syncthreads();

    // ---- horizontal 11-sum over all 50 rows, in place (cols 0..29) ----
    for (int t = tid; t < NDX*nrTot; t += 512){
        int d = t / nrTot, r = t - (t/nrTot)*nrTot;
        float* row = &sq[d*SQSTRIDE + r*HW];
        float v[HW];
        #pragma unroll
        for (int k = 0; k < HW/4; ++k){
            float4 tv = *(const float4*)&row[4*k];
            v[4*k+0]=tv.x; v[4*k+1]=tv.y; v[4*k+2]=tv.z; v[4*k+3]=tv.w;
        }
        float su = 0.f;
        #pragma unroll
        for (int j = 0; j < KS; ++j) su += v[j];
        row[0] = su;
        #pragma unroll
        for (int lx = 1; lx < HP; ++lx){
            su += v[lx+KS-1] - v[lx-1];
            row[lx] = su;
        }
    }
    __syncthreads();

    // ---- vertical 11-sum per (region, d, lx), in place ----
    for (int t = tid; t < 2*NDX*HP; t += 512){
        int rg  = t / (NDX*HP);
        int rem = t - rg*NDX*HP;
        int d = rem / HP, lx = rem - (rem/HP)*HP;
        int nrows = rg ? nrowsB : nrowsA;
        if (nrows == 0) continue;
        int rb = rg ? nrowsA : 0;
        int nly = nrows - (KS-1);
        float* colp = &sq[d*SQSTRIDE + lx];
        float v[HW];
        #pragma unroll
        for (int i = 0; i < HW; ++i) v[i] = (i < nrows) ? colp[(rb+i)*HW] : 0.f;
        float su = 0.f;
        #pragma unroll
        for (int j = 0; j < KS; ++j) su += v[j];
        #pragma unroll
        for (int o = 0; o < HP; ++o){
            if (o < nly) colp[(rb+o)*HW] = su;
            if (o+1 < HP) su += v[o+KS] - v[o];
        }
    }
    __syncthreads();

    // ---- per-output max over this block's dx set (exactly one region per py) ----
    unsigned* eout = &g_enc[b*HP*HP];
    for (int t = tid; t < HP*HP; t += 512){
        int py = t / HP, px = t - (t/HP)*HP;
        int rowSlot, ly;
        if (py <= p && p < 29){ rowSlot = py;                 ly = py - dyA; }
        else if (p >= 29)     { rowSlot = py;                 ly = py;       }
        else                  { rowSlot = nrowsA + (py-p-1);  ly = py - dyB; }
        if (ly < 0 || ly >= HP) continue;
        const float* base = &sq[rowSlot*HW];
        const float* svr  = &sinv[ly*HP];
        float m = -3.0e38f;
        bool any = false;
        #pragma unroll
        for (int d = 0; d < NDX; ++d){
            int dx = dxlo + d;
            int lx = px - dx;
            if (dx <= 29 && lx >= 0 && lx < HP){
                float v = base[d*SQSTRIDE + lx] * svr[lx];
                m = fmaxf(m, v);
                any = true;
            }
        }
        if (any) atomicMax(&eout[t], encf(m));
    }

    // ---- last block decodes ----
    __threadfence();
    __shared__ unsigned sLast;
    if (tid == 0) sLast = atomicAdd(&g_done, 1u);
    __syncthreads();
    if (sLast == TOTBLK - 1){
        for (int t = tid; t < OUTN; t += 512){
            unsigned e = g_enc[t];
            int v = (e & 0x80000000u) ? (int)(e ^ 0x80000000u) : ~(int)e;
            out[t] = __int_as_float(v);
        }
    }
}

extern "C" void kernel_launch(void* const* d_in, const int* in_sizes, int n_in,
                              void* d_out, int out_size){
    (void)in_sizes; (void)n_in; (void)out_size;
    const float* im1 = (const float*)d_in[0];
    const float* im2 = (const float*)d_in[1];

    const int smem_bytes = (NDX*SQSTRIDE + HP*HP) * (int)sizeof(float);
    cudaFuncSetAttribute(corr_kernel, cudaFuncAttributeMaxDynamicSharedMemorySize, smem_bytes);

    prep_kernel<<<64, 256>>>(im1, im2);
    norm_reduce<<<NB, 1024>>>();
    corr_kernel<<<dim3(4, 30, NB), 512, smem_bytes>>>(im1, (float*)d_out);
}

// round 13
// speedup vs baseline: 1.0871x; 1.0653x over previous
#include <cuda_runtime.h>

#define NB 4
#define NC 64
#define HW 40
#define KS 11
#define HP 30
#define PIX 1600          // 40*40
#define NDX 15            // dx shifts per block (4 groups; last has 14 live)
#define NG 16             // norm partial groups (4 channels each)
#define GUARD 64
#define OUTN (NB*HP*HP)

__device__ unsigned g_enc[OUTN];
__device__ float    g_inv[OUTN];
__device__ float    g_part[NB*NG*PIX];
__device__ __align__(16) float g_im2g[GUARD + NB*NC*PIX + GUARD];

__device__ __forceinline__ unsigned encf(float f){
    int b = __float_as_int(f);
    return (unsigned)(b ^ ((b >> 31) | 0x80000000));
}

// ---------------- K0a: 64 partial-sum blocks + 192 copy blocks ----------------
__global__ void __launch_bounds__(256) prep_kernel(const float* __restrict__ im1,
                                                   const float* __restrict__ im2){
    int blk = blockIdx.x;
    if (blk < NB*NG){
        int b = blk / NG, g = blk - (blk/NG)*NG;
        const float* base = im1 + ((size_t)b*NC + g*(NC/NG))*PIX;
        for (int p = threadIdx.x; p < PIX; p += 256){
            float acc = 0.f;
            #pragma unroll
            for (int c = 0; c < NC/NG; ++c){ float v = base[c*PIX + p]; acc += v*v; }
            g_part[(b*NG + g)*PIX + p] = acc;
        }
    } else {
        int cb = blk - NB*NG;                  // 0..191
        const int total4 = (NB*NC*PIX)/4;      // 102400 float4
        const float4* src = (const float4*)im2;
        float4* dst = (float4*)(g_im2g + GUARD);
        for (int i = cb*256 + threadIdx.x; i < total4; i += 192*256)
            dst[i] = src[i];
        if (cb == 0){
            for (int i = threadIdx.x; i < GUARD; i += 256){
                g_im2g[i] = 0.f;
                g_im2g[GUARD + NB*NC*PIX + i] = 0.f;
            }
        }
    }
}

// ---------------- K0b: reduce partials + 11x11 box sum -> inv norm ----------------
__global__ void __launch_bounds__(1024) norm_reduce(){
    __shared__ float sA[PIX];
    __shared__ float sH[HW*HP];
    int b = blockIdx.x;
    int tid = threadIdx.x;
    for (int p = tid; p < PIX; p += 1024){
        float acc = 0.f;
        #pragma unroll
        for (int g = 0; g < NG; ++g) acc += g_part[(b*NG + g)*PIX + p];
        sA[p] = acc;
    }
    __syncthreads();
    for (int t = tid; t < HW*HP; t += 1024){
        int y = t / HP, lx = t - y*HP;
        const float* row = &sA[y*HW];
        float s = 0.f;
        #pragma unroll
        for (int j = 0; j < KS; ++j) s += row[lx + j];
        sH[y*HP + lx] = s;
    }
    __syncthreads();
    for (int t = tid; t < HP*HP; t += 1024){
        int ly = t / HP, lx = t - ly*HP;
        float s = 0.f;
        #pragma unroll
        for (int i = 0; i < KS; ++i) s += sH[(ly+i)*HP + lx];
        float nrm = sqrtf(s);
        g_inv[b*HP*HP + t] = 1.0f / fmaxf(nrm, 1e-4f);
        g_enc[b*HP*HP + t] = 0u;
    }
}

// ---------------- mainloop: direct-LDG, zero barriers ----------------
template<int SH>
__device__ __forceinline__ void run_channels(
    const float* __restrict__ g1c,    // &im1[b][0][i1]
    const float* __restrict__ wpc,    // guarded im2 ptr at window start (16B aligned)
    float* __restrict__ q)
{
    #pragma unroll 1
    for (int c = 0; c < NC; ++c){
        float4 A = __ldg((const float4*)(g1c + (size_t)c*PIX));
        float w[24];
        #pragma unroll
        for (int k = 0; k < 6; ++k){
            float4 tv = __ldg((const float4*)(wpc + (size_t)c*PIX + 4*k));
            w[4*k+0]=tv.x; w[4*k+1]=tv.y; w[4*k+2]=tv.z; w[4*k+3]=tv.w;
        }
        #pragma unroll
        for (int d = 0; d < NDX; ++d){
            q[d*4+0] += A.x * w[SH+d+0];
            q[d*4+1] += A.y * w[SH+d+1];
            q[d*4+2] += A.z * w[SH+d+2];
            q[d*4+3] += A.w * w[SH+d+3];
        }
    }
}

// ---------------- epilogue for one dy: dump, box sums, max+atomic ----------------
__device__ void do_epi(float* __restrict__ sq, const float* __restrict__ sinv,
                       unsigned* __restrict__ eout, const float* __restrict__ q,
                       bool mine, int i1, int dy, int dxlo, int tid)
{
    if (mine){
        #pragma unroll
        for (int d = 0; d < NDX; ++d)
            *(float4*)&sq[d*PIX + i1] = make_float4(q[d*4+0],q[d*4+1],q[d*4+2],q[d*4+3]);
    }
    __syncthreads();

    int ady = (dy < 0) ? -dy : dy;
    int y0  = (dy < 0) ? -dy : 0;
    int nrows = HW - ady;

    // horizontal 11-sum (in place, cols 0..29)
    for (int t = tid; t < NDX*nrows; t += 512){
        int d = t / nrows;
        int y = y0 + (t - d*nrows);
        float* row = &sq[d*PIX + y*HW];
        float r[HW];
        #pragma unroll
        for (int k = 0; k < HW/4; ++k){
            float4 tv = *(const float4*)&row[4*k];
            r[4*k+0]=tv.x; r[4*k+1]=tv.y; r[4*k+2]=tv.z; r[4*k+3]=tv.w;
        }
        float s = 0.f;
        #pragma unroll
        for (int j = 0; j < KS; ++j) s += r[j];
        row[0] = s;
        #pragma unroll
        for (int lx = 1; lx < HP; ++lx){
            s += r[lx+KS-1] - r[lx-1];
            row[lx] = s;
        }
    }
    __syncthreads();

    // vertical 11-sum (in place)
    int ly0 = y0;
    int nly = HP - ady;
    for (int t = tid; t < NDX*HP; t += 512){
        int d = t / HP, lx = t - (t/HP)*HP;
        float* colp = &sq[d*PIX + lx];
        int cnt = nly + KS - 1;
        float v[HW];
        #pragma unroll
        for (int i = 0; i < HW; ++i) v[i] = (i < cnt) ? colp[(ly0+i)*HW] : 0.f;
        float s = 0.f;
        #pragma unroll
        for (int j = 0; j < KS; ++j) s += v[j];
        #pragma unroll
        for (int o = 0; o < HP; ++o){
            if (o < nly) colp[(ly0+o)*HW] = s;
            if (o+1 < HP) s += v[o+KS] - v[o];
        }
    }
    __syncthreads();

    // per-output max over this block's dx set, one atomicMax per p
    for (int t = tid; t < HP*HP; t += 512){
        int py = t / HP, px = t - (t/HP)*HP;
        int ly = py - dy;
        if (ly < 0 || ly >= HP) continue;
        float m = -3.0e38f;
        bool any = false;
        #pragma unroll
        for (int d = 0; d < NDX; ++d){
            int dx = dxlo + d;
            int lx = px - dx;
            if (dx <= 29 && lx >= 0 && lx < HP){
                float v = sq[d*PIX + ly*HW + lx] * sinv[ly*HP + lx];
                m = fmaxf(m, v);
                any = true;
            }
        }
        if (any) atomicMax(&eout[t], encf(m));
    }
    __syncthreads();   // sq free for next pass
}

// ---------------- K1: paired-dy correlation, barrier-free mainloop ----------------
// grid: (4 dx-groups, 30 dy-pairs, 4 batch), 512 threads
__global__ void __launch_bounds__(512, 1) corr_kernel(const float* __restrict__ im1){
    extern __shared__ float smem[];
    float* sq   = smem;                  // [NDX*1600]
    float* sinv = sq + NDX*PIX;          // [900]

    int tid = threadIdx.x;
    int gx  = blockIdx.x;
    int p   = blockIdx.y;
    int b   = blockIdx.z;
    int dxlo = -29 + NDX*gx;

    int dyA, dyB, cntA, cntB;
    if (p < 29){ dyA = p - 29; dyB = p + 1; cntA = (11+p)*10; cntB = (39-p)*10; }
    else       { dyA = 0;      dyB = 0;     cntA = 400;       cntB = 0;        }

    for (int i = tid; i < HP*HP; i += 512) sinv[i] = g_inv[b*HP*HP + i];

    bool act = tid < cntA + cntB;
    int myDy, s;
    if (tid < cntA){ myDy = dyA; s = tid; } else { myDy = dyB; s = tid - cntA; }
    int y0t = (myDy < 0) ? -myDy : 0;
    int sy = y0t + s/10;
    int sx = (s - (s/10)*10)*4;
    int i1 = sy*HW + sx;

    const float* g1c = im1 + (size_t)b*NC*PIX + i1;
    const float* wbase = g_im2g + GUARD + (size_t)b*NC*PIX + (sy + myDy)*HW + sx + dxlo;

    float q[NDX*4];
    #pragma unroll
    for (int i = 0; i < NDX*4; ++i) q[i] = 0.f;

    if (act){
        switch (gx){
            case 0: run_channels<3>(g1c, wbase-3, q); break;
            case 1: run_channels<6>(g1c, wbase-6, q); break;
            case 2: run_channels<5>(g1c, wbase-5, q); break;
            default: run_channels<4>(g1c, wbase-4, q); break;
        }
    }

    unsigned* eout = &g_enc[b*HP*HP];
    do_epi(sq, sinv, eout, q, tid < cntA, i1, dyA, dxlo, tid);
    if (cntB > 0)
        do_epi(sq, sinv, eout, q, act && tid >= cntA, i1, dyB, dxlo, tid);
}

// ---------------- K2: decode ----------------
__global__ void decode_kernel(float* __restrict__ out){
    int t = blockIdx.x*blockDim.x + threadIdx.x;
    if (t < OUTN){
        unsigned e = g_enc[t];
        int v = (e & 0x80000000u) ? (int)(e ^ 0x80000000u) : ~(int)e;
        out[t] = __int_as_float(v);
    }
}

extern "C" void kernel_launch(void* const* d_in, const int* in_sizes, int n_in,
                              void* d_out, int out_size){
    (void)in_sizes; (void)n_in; (void)out_size;
    const float* im1 = (const float*)d_in[0];
    const float* im2 = (const float*)d_in[1];

    const int smem_bytes = (NDX*PIX + HP*HP) * (int)sizeof(float);
    cudaFuncSetAttribute(corr_kernel, cudaFuncAttributeMaxDynamicSharedMemorySize, smem_bytes);

    prep_kernel<<<256, 256>>>(im1, im2);
    norm_reduce<<<NB, 1024>>>();
    corr_kernel<<<dim3(4, 30, NB), 512, smem_bytes>>>(im1);
    decode_kernel<<<(OUTN + 255)/256, 256>>>((float*)d_out);
}

// round 16
// speedup vs baseline: 1.3719x; 1.2620x over previous
#include <cuda_runtime.h>
#include <cstdint>

#define NB 4
#define NC 64
#define HW 40
#define KS 11
#define HP 30
#define PIX 1600
#define NDX 15
#define NG 16
#define OUTN (NB*HP*HP)

#define GROW 1600
#define GSZ (GROW*GROW)
#define GG 64
#define SMSTR 68            // padded k-stride for smem fragment arrays

__device__ unsigned g_enc[OUTN];
__device__ float    g_inv[OUTN];
__device__ float    g_part[NB*NG*PIX];
__device__ __align__(16) float g_G[2*GG + NB*GSZ];

extern __shared__ float dynsmem[];

__device__ __forceinline__ unsigned encf(float f){
    int b = __float_as_int(f);
    return (unsigned)(b ^ ((b >> 31) | 0x80000000));
}

__device__ __forceinline__ uint32_t to_tf32(float f){
    uint32_t u;
    asm("cvt.rna.tf32.f32 %0, %1;" : "=r"(u) : "f"(f));
    return u;
}

// ---------------- K0a: norm partials + G guard zero ----------------
__global__ void __launch_bounds__(256) prep_kernel(const float* __restrict__ im1){
    int blk = blockIdx.x;
    if (blk < NB*NG){
        int b = blk / NG, g = blk - (blk/NG)*NG;
        const float* base = im1 + ((size_t)b*NC + g*(NC/NG))*PIX;
        for (int p = threadIdx.x; p < PIX; p += 256){
            float acc = 0.f;
            #pragma unroll
            for (int c = 0; c < NC/NG; ++c){ float v = base[c*PIX + p]; acc += v*v; }
            g_part[(b*NG + g)*PIX + p] = acc;
        }
    } else {
        if (threadIdx.x < GG){
            g_G[threadIdx.x] = 0.f;
            g_G[GG + NB*GSZ + threadIdx.x] = 0.f;
        }
    }
}

// ---------------- K0b: reduce + 11x11 box sum -> inv norm ----------------
__global__ void __launch_bounds__(1024) norm_reduce(){
    __shared__ float sA[PIX];
    __shared__ float sH[HW*HP];
    int b = blockIdx.x;
    int tid = threadIdx.x;
    for (int p = tid; p < PIX; p += 1024){
        float acc = 0.f;
        #pragma unroll
        for (int g = 0; g < NG; ++g) acc += g_part[(b*NG + g)*PIX + p];
        sA[p] = acc;
    }
    __syncthreads();
    for (int t = tid; t < HW*HP; t += 1024){
        int y = t / HP, lx = t - y*HP;
        const float* row = &sA[y*HW];
        float s = 0.f;
        #pragma unroll
        for (int j = 0; j < KS; ++j) s += row[lx + j];
        sH[y*HP + lx] = s;
    }
    __syncthreads();
    for (int t = tid; t < HP*HP; t += 1024){
        int ly = t / HP, lx = t - ly*HP;
        float s = 0.f;
        #pragma unroll
        for (int i = 0; i < KS; ++i) s += sH[(ly+i)*HP + lx];
        float nrm = sqrtf(s);
        g_inv[b*HP*HP + t] = 1.0f / fmaxf(nrm, 1e-4f);
        g_enc[b*HP*HP + t] = 0u;
    }
}

// ---------------- GEMM: G[b] = im1[b]^T @ im2[b], split-tf32 mma.sync ----------------
// grid (13, 13, NB), 256 threads (8 warps, 2x4), block tile 128x128, K=64.
__global__ void __launch_bounds__(256) gemm_kernel(const float* __restrict__ im1,
                                                   const float* __restrict__ im2){
    uint32_t* sAh = (uint32_t*)dynsmem;            // [128][SMSTR]
    uint32_t* sAl = sAh + 128*SMSTR;
    uint32_t* sBh = sAl + 128*SMSTR;
    uint32_t* sBl = sBh + 128*SMSTR;

    int tid = threadIdx.x;
    int b = blockIdx.z;
    int m0 = (blockIdx.x < 12) ? blockIdx.x*128 : (GROW - 128);
    int n0 = (blockIdx.y < 12) ? blockIdx.y*128 : (GROW - 128);

    const float* p1 = im1 + (size_t)b*NC*PIX;
    const float* p2 = im2 + (size_t)b*NC*PIX;

    // stage A and B as split tf32, layout [row][k] stride SMSTR
    {
        int r = tid & 127, half = tid >> 7;
        #pragma unroll
        for (int h = 0; h < 32; ++h){
            int c = h*2 + half;
            float va = p1[(size_t)c*PIX + m0 + r];
            float vb = p2[(size_t)c*PIX + n0 + r];
            uint32_t ah = to_tf32(va);
            uint32_t bh = to_tf32(vb);
            uint32_t al = to_tf32(va - __uint_as_float(ah));
            uint32_t bl = to_tf32(vb - __uint_as_float(bh));
            sAh[r*SMSTR + c] = ah;  sAl[r*SMSTR + c] = al;
            sBh[r*SMSTR + c] = bh;  sBl[r*SMSTR + c] = bl;
        }
    }
    __syncthreads();

    int w = tid >> 5, lane = tid & 31;
    int g = lane >> 2, tg = lane & 3;
    int wm = (w & 1)*64, wn = (w >> 1)*32;

    float acc[4][4][4];
    #pragma unroll
    for (int i = 0; i < 4; ++i)
        #pragma unroll
        for (int j = 0; j < 4; ++j)
            #pragma unroll
            for (int k = 0; k < 4; ++k) acc[i][j][k] = 0.f;

    #pragma unroll
    for (int pass = 0; pass < 3; ++pass){
        const uint32_t* A = (pass == 2) ? sAl : sAh;
        const uint32_t* B = (pass == 1) ? sBl : sBh;
        #pragma unroll
        for (int ks = 0; ks < 8; ++ks){
            int k0 = ks*8;
            uint32_t bf[4][2];
            #pragma unroll
            for (int nt = 0; nt < 4; ++nt){
                int base = (wn + nt*8 + g)*SMSTR + k0 + tg;
                bf[nt][0] = B[base];
                bf[nt][1] = B[base + 4];
            }
            #pragma unroll
            for (int mt = 0; mt < 4; ++mt){
                int base = (wm + mt*16 + g)*SMSTR + k0 + tg;
                uint32_t a0 = A[base], a1 = A[base + 8*SMSTR];
                uint32_t a2 = A[base + 4], a3 = A[base + 8*SMSTR + 4];
                #pragma unroll
                for (int nt = 0; nt < 4; ++nt){
                    asm volatile(
                        "mma.sync.aligned.m16n8k8.row.col.f32.tf32.tf32.f32 "
                        "{%0,%1,%2,%3}, {%4,%5,%6,%7}, {%8,%9}, {%0,%1,%2,%3};"
                        : "+f"(acc[mt][nt][0]), "+f"(acc[mt][nt][1]),
                          "+f"(acc[mt][nt][2]), "+f"(acc[mt][nt][3])
                        : "r"(a0), "r"(a1), "r"(a2), "r"(a3),
                          "r"(bf[nt][0]), "r"(bf[nt][1]));
                }
            }
        }
    }

    float* gout = g_G + GG + (size_t)b*GSZ;
    #pragma unroll
    for (int mt = 0; mt < 4; ++mt){
        int row = m0 + wm + mt*16 + g;
        #pragma unroll
        for (int nt = 0; nt < 4; ++nt){
            int col = n0 + wn + nt*8 + 2*tg;
            *(float2*)&gout[(size_t)row*GROW + col]     = make_float2(acc[mt][nt][0], acc[mt][nt][1]);
            *(float2*)&gout[(size_t)(row+8)*GROW + col] = make_float2(acc[mt][nt][2], acc[mt][nt][3]);
        }
    }
}

// ---------------- q fill from G diagonal bands ----------------
template<int CM>
__device__ __forceinline__ void fill_q(const float* __restrict__ gb, int i1, int colbase,
                                       float* __restrict__ q){
    #pragma unroll
    for (int j = 0; j < 4; ++j){
        const int mis = (CM + j) & 3;
        const float* gr = gb + (size_t)(i1 + j)*GROW + (colbase + j - mis);
        float w[20];
        #pragma unroll
        for (int k = 0; k < 5; ++k){
            float4 t = __ldg((const float4*)(gr + 4*k));
            w[4*k+0]=t.x; w[4*k+1]=t.y; w[4*k+2]=t.z; w[4*k+3]=t.w;
        }
        #pragma unroll
        for (int d = 0; d < NDX; ++d) q[d*4 + j] = w[mis + d];
    }
}

// ---------------- epilogue for one dy (verbatim from 113us champion) ----------------
__device__ void do_epi(float* __restrict__ sq, const float* __restrict__ sinv,
                       unsigned* __restrict__ eout, const float* __restrict__ q,
                       bool mine, int i1, int dy, int dxlo, int tid)
{
    if (mine){
        #pragma unroll
        for (int d = 0; d < NDX; ++d)
            *(float4*)&sq[d*PIX + i1] = make_float4(q[d*4+0],q[d*4+1],q[d*4+2],q[d*4+3]);
    }
    __syncthreads();

    int ady = (dy < 0) ? -dy : dy;
    int y0  = (dy < 0) ? -dy : 0;
    int nrows = HW - ady;

    for (int t = tid; t < NDX*nrows; t += 512){
        int d = t / nrows;
        int y = y0 + (t - d*nrows);
        float* row = &sq[d*PIX + y*HW];
        float r[HW];
        #pragma unroll
        for (int k = 0; k < HW/4; ++k){
            float4 tv = *(const float4*)&row[4*k];
            r[4*k+0]=tv.x; r[4*k+1]=tv.y; r[4*k+2]=tv.z; r[4*k+3]=tv.w;
        }
        float s = 0.f;
        #pragma unroll
        for (int j = 0; j < KS; ++j) s += r[j];
        row[0] = s;
        #pragma unroll
        for (int lx = 1; lx < HP; ++lx){
            s += r[lx+KS-1] - r[lx-1];
            row[lx] = s;
        }
    }
    __syncthreads();

    int ly0 = y0;
    int nly = HP - ady;
    for (int t = tid; t < NDX*HP; t += 512){
        int d = t / HP, lx = t - (t/HP)*HP;
        float* colp = &sq[d*PIX + lx];
        int cnt = nly + KS - 1;
        float v[HW];
        #pragma unroll
        for (int i = 0; i < HW; ++i) v[i] = (i < cnt) ? colp[(ly0+i)*HW] : 0.f;
        float s = 0.f;
        #pragma unroll
        for (int j = 0; j < KS; ++j) s += v[j];
        #pragma unroll
        for (int o = 0; o < HP; ++o){
            if (o < nly) colp[(ly0+o)*HW] = s;
            if (o+1 < HP) s += v[o+KS] - v[o];
        }
    }
    __syncthreads();

    for (int t = tid; t < HP*HP; t += 512){
        int py = t / HP, px = t - (t/HP)*HP;
        int ly = py - dy;
        if (ly < 0 || ly >= HP) continue;
        float m = -3.0e38f;
        bool any = false;
        #pragma unroll
        for (int d = 0; d < NDX; ++d){
            int dx = dxlo + d;
            int lx = px - dx;
            if (dx <= 29 && lx >= 0 && lx < HP){
                float v = sq[d*PIX + ly*HW + lx] * sinv[ly*HP + lx];
                m = fmaxf(m, v);
                any = true;
            }
        }
        if (any) atomicMax(&eout[t], encf(m));
    }
    __syncthreads();
}

// ---------------- K1: paired-dy, q filled from G ----------------
__global__ void __launch_bounds__(512, 1) corr_kernel(){
    float* sq   = dynsmem;               // [NDX*1600]
    float* sinv = sq + NDX*PIX;          // [900]

    int tid = threadIdx.x;
    int gx  = blockIdx.x;
    int p   = blockIdx.y;
    int b   = blockIdx.z;
    int dxlo = -29 + NDX*gx;

    int dyA, dyB, cntA, cntB;
    if (p < 29){ dyA = p - 29; dyB = p + 1; cntA = (11+p)*10; cntB = (39-p)*10; }
    else       { dyA = 0;      dyB = 0;     cntA = 400;       cntB = 0;        }

    for (int i = tid; i < HP*HP; i += 512) sinv[i] = g_inv[b*HP*HP + i];

    bool act = tid < cntA + cntB;
    int myDy, s;
    if (tid < cntA){ myDy = dyA; s = tid; } else { myDy = dyB; s = tid - cntA; }
    int y0t = (myDy < 0) ? -myDy : 0;
    int sy = y0t + s/10;
    int sx = (s - (s/10)*10)*4;
    int i1 = sy*HW + sx;

    const float* gb = g_G + GG + (size_t)b*GSZ;
    int colbase = (sy + myDy)*HW + sx + dxlo;

    float q[NDX*4];
    #pragma unroll
    for (int i = 0; i < NDX*4; ++i) q[i] = 0.f;

    if (act){
        switch (gx){
            case 0: fill_q<3>(gb, i1, colbase, q); break;   // dxlo=-29 mod 4 = 3
            case 1: fill_q<2>(gb, i1, colbase, q); break;   // dxlo=-14 mod 4 = 2
            case 2: fill_q<1>(gb, i1, colbase, q); break;   // dxlo=  1 mod 4 = 1
            default: fill_q<0>(gb, i1, colbase, q); break;  // dxlo= 16 mod 4 = 0
        }
    }

    unsigned* eout = &g_enc[b*HP*HP];
    do_epi(sq, sinv, eout, q, tid < cntA, i1, dyA, dxlo, tid);
    if (cntB > 0)
        do_epi(sq, sinv, eout, q, act && tid >= cntA, i1, dyB, dxlo, tid);
}

// ---------------- K2: decode ----------------
__global__ void decode_kernel(float* __restrict__ out){
    int t = blockIdx.x*blockDim.x + threadIdx.x;
    if (t < OUTN){
        unsigned e = g_enc[t];
        int v = (e & 0x80000000u) ? (int)(e ^ 0x80000000u) : ~(int)e;
        out[t] = __int_as_float(v);
    }
}

extern "C" void kernel_launch(void* const* d_in, const int* in_sizes, int n_in,
                              void* d_out, int out_size){
    (void)in_sizes; (void)n_in; (void)out_size;
    const float* im1 = (const float*)d_in[0];
    const float* im2 = (const float*)d_in[1];

    const int corr_smem = (NDX*PIX + HP*HP) * (int)sizeof(float);
    const int gemm_smem = 4 * 128 * SMSTR * (int)sizeof(uint32_t);
    cudaFuncSetAttribute(corr_kernel, cudaFuncAttributeMaxDynamicSharedMemorySize, corr_smem);
    cudaFuncSetAttribute(gemm_kernel, cudaFuncAttributeMaxDynamicSharedMemorySize, gemm_smem);

    prep_kernel<<<NB*NG + 1, 256>>>(im1);
    norm_reduce<<<NB, 1024>>>();
    gemm_kernel<<<dim3(13, 13, NB), 256, gemm_smem>>>(im1, im2);
    corr_kernel<<<dim3(4, 30, NB), 512, corr_smem>>>();
    decode_kernel<<<(OUTN + 255)/256, 256>>>((float*)d_out);
}

// round 17
// speedup vs baseline: 1.3912x; 1.0141x over previous
#include <cuda_runtime.h>
#include <cstdint>

#define NB 4
#define NC 64
#define HW 40
#define KS 11
#define HP 30
#define PIX 1600
#define NDX 8              // dx shifts per block (8 groups; last has 3 live)
#define NG 16
#define OUTN (NB*HP*HP)

#define GROW 1600
#define GSZ (GROW*GROW)
#define GG 64
#define SMSTR 68           // padded k-stride for gemm smem
#define SQSTRIDE 2000      // 50 rows * 40 cols per d slice

__device__ unsigned g_enc[OUTN];
__device__ float    g_inv[OUTN];
__device__ float    g_part[NB*NG*PIX];
__device__ __align__(16) float g_G[2*GG + NB*GSZ];

extern __shared__ float dynsmem[];

__device__ __forceinline__ unsigned encf(float f){
    int b = __float_as_int(f);
    return (unsigned)(b ^ ((b >> 31) | 0x80000000));
}

__device__ __forceinline__ uint32_t to_tf32(float f){
    uint32_t u;
    asm("cvt.rna.tf32.f32 %0, %1;" : "=r"(u) : "f"(f));
    return u;
}

// ---------------- K0a: norm partials + G guard zero ----------------
__global__ void __launch_bounds__(256) prep_kernel(const float* __restrict__ im1){
    int blk = blockIdx.x;
    if (blk < NB*NG){
        int b = blk / NG, g = blk - (blk/NG)*NG;
        const float* base = im1 + ((size_t)b*NC + g*(NC/NG))*PIX;
        for (int p = threadIdx.x; p < PIX; p += 256){
            float acc = 0.f;
            #pragma unroll
            for (int c = 0; c < NC/NG; ++c){ float v = base[c*PIX + p]; acc += v*v; }
            g_part[(b*NG + g)*PIX + p] = acc;
        }
    } else {
        if (threadIdx.x < GG){
            g_G[threadIdx.x] = 0.f;
            g_G[GG + NB*GSZ + threadIdx.x] = 0.f;
        }
    }
}

// ---------------- K0b: reduce + 11x11 box sum -> inv norm ----------------
__global__ void __launch_bounds__(1024) norm_reduce(){
    __shared__ float sA[PIX];
    __shared__ float sH[HW*HP];
    int b = blockIdx.x;
    int tid = threadIdx.x;
    for (int p = tid; p < PIX; p += 1024){
        float acc = 0.f;
        #pragma unroll
        for (int g = 0; g < NG; ++g) acc += g_part[(b*NG + g)*PIX + p];
        sA[p] = acc;
    }
    __syncthreads();
    for (int t = tid; t < HW*HP; t += 1024){
        int y = t / HP, lx = t - y*HP;
        const float* row = &sA[y*HW];
        float s = 0.f;
        #pragma unroll
        for (int j = 0; j < KS; ++j) s += row[lx + j];
        sH[y*HP + lx] = s;
    }
    __syncthreads();
    for (int t = tid; t < HP*HP; t += 1024){
        int ly = t / HP, lx = t - ly*HP;
        float s = 0.f;
        #pragma unroll
        for (int i = 0; i < KS; ++i) s += sH[(ly+i)*HP + lx];
        float nrm = sqrtf(s);
        g_inv[b*HP*HP + t] = 1.0f / fmaxf(nrm, 1e-4f);
        g_enc[b*HP*HP + t] = 0u;
    }
}

// ---------------- GEMM: G[b] = im1[b]^T @ im2[b], split-tf32 mma.sync ----------------
__global__ void __launch_bounds__(256) gemm_kernel(const float* __restrict__ im1,
                                                   const float* __restrict__ im2){
    uint32_t* sAh = (uint32_t*)dynsmem;            // [128][SMSTR]
    uint32_t* sAl = sAh + 128*SMSTR;
    uint32_t* sBh = sAl + 128*SMSTR;
    uint32_t* sBl = sBh + 128*SMSTR;

    int tid = threadIdx.x;
    int b = blockIdx.z;
    int m0 = (blockIdx.x < 12) ? blockIdx.x*128 : (GROW - 128);
    int n0 = (blockIdx.y < 12) ? blockIdx.y*128 : (GROW - 128);
    int dd = m0 - n0; if (dd < 0) dd = -dd;
    if (dd > 1316) return;               // band never read by corr (incl. guard overhang)

    const float* p1 = im1 + (size_t)b*NC*PIX;
    const float* p2 = im2 + (size_t)b*NC*PIX;

    {
        int r = tid & 127, half = tid >> 7;
        #pragma unroll
        for (int h = 0; h < 32; ++h){
            int c = h*2 + half;
            float va = p1[(size_t)c*PIX + m0 + r];
            float vb = p2[(size_t)c*PIX + n0 + r];
            uint32_t ah = to_tf32(va);
            uint32_t bh = to_tf32(vb);
            uint32_t al = to_tf32(va - __uint_as_float(ah));
            uint32_t bl = to_tf32(vb - __uint_as_float(bh));
            sAh[r*SMSTR + c] = ah;  sAl[r*SMSTR + c] = al;
            sBh[r*SMSTR + c] = bh;  sBl[r*SMSTR + c] = bl;
        }
    }
    __syncthreads();

    int w = tid >> 5, lane = tid & 31;
    int g = lane >> 2, tg = lane & 3;
    int wm = (w & 1)*64, wn = (w >> 1)*32;

    float acc[4][4][4];
    #pragma unroll
    for (int i = 0; i < 4; ++i)
        #pragma unroll
        for (int j = 0; j < 4; ++j)
            #pragma unroll
            for (int k = 0; k < 4; ++k) acc[i][j][k] = 0.f;

    #pragma unroll
    for (int pass = 0; pass < 3; ++pass){
        const uint32_t* A = (pass == 2) ? sAl : sAh;
        const uint32_t* B = (pass == 1) ? sBl : sBh;
        #pragma unroll
        for (int ks = 0; ks < 8; ++ks){
            int k0 = ks*8;
            uint32_t bf[4][2];
            #pragma unroll
            for (int nt = 0; nt < 4; ++nt){
                int base = (wn + nt*8 + g)*SMSTR + k0 + tg;
                bf[nt][0] = B[base];
                bf[nt][1] = B[base + 4];
            }
            #pragma unroll
            for (int mt = 0; mt < 4; ++mt){
                int base = (wm + mt*16 + g)*SMSTR + k0 + tg;
                uint32_t a0 = A[base], a1 = A[base + 8*SMSTR];
                uint32_t a2 = A[base + 4], a3 = A[base + 8*SMSTR + 4];
                #pragma unroll
                for (int nt = 0; nt < 4; ++nt){
                    asm volatile(
                        "mma.sync.aligned.m16n8k8.row.col.f32.tf32.tf32.f32 "
                        "{%0,%1,%2,%3}, {%4,%5,%6,%7}, {%8,%9}, {%0,%1,%2,%3};"
                        : "+f"(acc[mt][nt][0]), "+f"(acc[mt][nt][1]),
                          "+f"(acc[mt][nt][2]), "+f"(acc[mt][nt][3])
                        : "r"(a0), "r"(a1), "r"(a2), "r"(a3),
                          "r"(bf[nt][0]), "r"(bf[nt][1]));
                }
            }
        }
    }

    float* gout = g_G + GG + (size_t)b*GSZ;
    #pragma unroll
    for (int mt = 0; mt < 4; ++mt){
        int row = m0 + wm + mt*16 + g;
        #pragma unroll
        for (int nt = 0; nt < 4; ++nt){
            int col = n0 + wn + nt*8 + 2*tg;
            *(float2*)&gout[(size_t)row*GROW + col]     = make_float2(acc[mt][nt][0], acc[mt][nt][1]);
            *(float2*)&gout[(size_t)(row+8)*GROW + col] = make_float2(acc[mt][nt][2], acc[mt][nt][3]);
        }
    }
}

// ---------------- K1: paired-dy, q from G bands, merged epilogue, 2 CTA/SM ----------------
// grid: (8 dx-groups, 30 dy-pairs, 4 batch), 512 threads
__global__ void __launch_bounds__(512, 2) corr_kernel(){
    float* sq   = dynsmem;               // [NDX][50][40]
    float* sinv = sq + NDX*SQSTRIDE;     // [900]

    int tid = threadIdx.x;
    int gx  = blockIdx.x;
    int p   = blockIdx.y;
    int b   = blockIdx.z;
    int dxlo = -29 + NDX*gx;             // all ≡ 3 (mod 4)

    int dyA, dyB, nrowsA, nrowsB;
    if (p < 29){ dyA = p - 29; dyB = p + 1; nrowsA = 11+p; nrowsB = 39-p; }
    else       { dyA = 0;      dyB = 0;     nrowsA = 40;   nrowsB = 0;   }
    int cntA = nrowsA*10, cntB = nrowsB*10;
    int nrTot = nrowsA + nrowsB;

    for (int i = tid; i < HP*HP; i += 512) sinv[i] = g_inv[b*HP*HP + i];

    bool act = tid < cntA + cntB;
    int myDy, s, rBase;
    if (tid < cntA){ myDy = dyA; s = tid; rBase = 0; }
    else           { myDy = dyB; s = tid - cntA; rBase = nrowsA; }
    int y0t = (myDy < 0) ? -myDy : 0;
    int rr = s/10;
    int sy = y0t + rr;
    int sx = (s - rr*10)*4;
    int i1 = sy*HW + sx;
    int rD = rBase + rr;

    const float* gb = g_G + GG + (size_t)b*GSZ;
    int colbase = (sy + myDy)*HW + sx + dxlo;

    // ---- fill q from G diagonal bands, dump immediately (q dead after) ----
    if (act){
        float q[NDX*4];
        #pragma unroll
        for (int j = 0; j < 4; ++j){
            const int mis = (3 + j) & 3;
            const float* gr = gb + (size_t)(i1 + j)*GROW + (colbase + j - mis);
            float w[12];
            #pragma unroll
            for (int k = 0; k < 3; ++k){
                float4 t = __ldg((const float4*)(gr + 4*k));
                w[4*k+0]=t.x; w[4*k+1]=t.y; w[4*k+2]=t.z; w[4*k+3]=t.w;
            }
            #pragma unroll
            for (int d = 0; d < NDX; ++d) q[d*4 + j] = w[mis + d];
        }
        #pragma unroll
        for (int d = 0; d < NDX; ++d)
            *(float4*)&sq[d*SQSTRIDE + rD*HW + sx] =
                make_float4(q[d*4+0], q[d*4+1], q[d*4+2], q[d*4+3]);
    }
    __syncthreads();

    // ---- horizontal 11-sum over all 50 rows, in place (cols 0..29) ----
    for (int t = tid; t < NDX*nrTot; t += 512){
        int d = t / nrTot, r = t - (t/nrTot)*nrTot;
        float* row = &sq[d*SQSTRIDE + r*HW];
        float v[HW];
        #pragma unroll
        for (int k = 0; k < HW/4; ++k){
            float4 tv = *(const float4*)&row[4*k];
            v[4*k+0]=tv.x; v[4*k+1]=tv.y; v[4*k+2]=tv.z; v[4*k+3]=tv.w;
        }
        float su = 0.f;
        #pragma unroll
        for (int j = 0; j < KS; ++j) su += v[j];
        row[0] = su;
        #pragma unroll
        for (int lx = 1; lx < HP; ++lx){
            su += v[lx+KS-1] - v[lx-1];
            row[lx] = su;
        }
    }
    __syncthreads();

    // ---- vertical 11-sum per (region, d, lx), in place ----
    for (int t = tid; t < 2*NDX*HP; t += 512){
        int rg  = t / (NDX*HP);
        int rem = t - rg*NDX*HP;
        int d = rem / HP, lx = rem - (rem/HP)*HP;
        int nrows = rg ? nrowsB : nrowsA;
        if (nrows == 0) continue;
        int rb = rg ? nrowsA : 0;
        int nly = nrows - (KS-1);
        float* colp = &sq[d*SQSTRIDE + lx];
        float v[HW];
        #pragma unroll
        for (int i = 0; i < HW; ++i) v[i] = (i < nrows) ? colp[(rb+i)*HW] : 0.f;
        float su = 0.f;
        #pragma unroll
        for (int j = 0; j < KS; ++j) su += v[j];
        #pragma unroll
        for (int o = 0; o < HP; ++o){
            if (o < nly) colp[(rb+o)*HW] = su;
            if (o+1 < HP) su += v[o+KS] - v[o];
        }
    }
    __syncthreads();

    // ---- per-output max over this block's dx set (exactly one region per py) ----
    unsigned* eout = &g_enc[b*HP*HP];
    for (int t = tid; t < HP*HP; t += 512){
        int py = t / HP, px = t - (t/HP)*HP;
        int rowSlot, ly;
        if (py <= p && p < 29){ rowSlot = py;                 ly = py - dyA; }
        else if (p >= 29)     { rowSlot = py;                 ly = py;       }
        else                  { rowSlot = nrowsA + (py-p-1);  ly = py - dyB; }
        if (ly < 0 || ly >= HP) continue;
        const float* base = &sq[rowSlot*HW];
        const float* svr  = &sinv[ly*HP];
        float m = -3.0e38f;
        bool any = false;
        #pragma unroll
        for (int d = 0; d < NDX; ++d){
            int dx = dxlo + d;
            int lx = px - dx;
            if (dx <= 29 && lx >= 0 && lx < HP){
                float v = base[d*SQSTRIDE + lx] * svr[lx];
                m = fmaxf(m, v);
                any = true;
            }
        }
        if (any) atomicMax(&eout[t], encf(m));
    }
}

// ---------------- K2: decode ----------------
__global__ void decode_kernel(float* __restrict__ out){
    int t = blockIdx.x*blockDim.x + threadIdx.x;
    if (t < OUTN){
        unsigned e = g_enc[t];
        int v = (e & 0x80000000u) ? (int)(e ^ 0x80000000u) : ~(int)e;
        out[t] = __int_as_float(v);
    }
}

extern "C" void kernel_launch(void* const* d_in, const int* in_sizes, int n_in,
                              void* d_out, int out_size){
    (void)in_sizes; (void)n_in; (void)out_size;
    const float* im1 = (const float*)d_in[0];
    const float* im2 = (const float*)d_in[1];

    const int corr_smem = (NDX*SQSTRIDE + HP*HP) * (int)sizeof(float);
    const int gemm_smem = 4 * 128 * SMSTR * (int)sizeof(uint32_t);
    cudaFuncSetAttribute(corr_kernel, cudaFuncAttributeMaxDynamicSharedMemorySize, corr_smem);
    cudaFuncSetAttribute(gemm_kernel, cudaFuncAttributeMaxDynamicSharedMemorySize, gemm_smem);

    prep_kernel<<<NB*NG + 1, 256>>>(im1);
    norm_reduce<<<NB, 1024>>>();
    gemm_kernel<<<dim3(13, 13, NB), 256, gemm_smem>>>(im1, im2);
    corr_kernel<<<dim3(8, 30, NB), 512, corr_smem>>>();
    decode_kernel<<<(OUTN + 255)/256, 256>>>((float*)d_out);
}